// round 6
// baseline (speedup 1.0000x reference)
#include <cuda_runtime.h>
#include <cuda_bf16.h>

#define GROUPS   512
#define ARITY    2
#define OUT_DIM  16
#define GPB      64   // groups per block (64 groups * 4 dim-quads = 256 threads)
#define B_ITER   16   // batch rows per thread

// out[b, g*16 + d] = bilinear interp of params[g, 0..3, d] at
// (u, v) = ((clip(x0,-1,1)+1)/2, (clip(x1,-1,1)+1)/2).
// Exact algebraic collapse of the midpoint-expanded 3x3 hat-basis contraction.
__global__ __launch_bounds__(256) void corner_bilinear_kernel(
    const float* __restrict__ X,
    const float* __restrict__ params,
    float* __restrict__ out,
    int batch)
{
    const int tid = threadIdx.x;
    const int q   = tid & 3;          // dim-quad 0..3 (4 floats each)
    const int gl  = tid >> 2;         // local group 0..63
    const int g   = blockIdx.x * GPB + gl;
    const int b0  = blockIdx.y * B_ITER;

    // params[g, c, d]: float4 index = g*16 + c*4 + q
    const float4* P = reinterpret_cast<const float4*>(params) + (size_t)g * 16 + q;
    const float4 p0 = __ldg(P + 0);   // corner (c0=0, c1=0) -> weight (1-u)(1-v)
    const float4 p1 = __ldg(P + 4);   // corner (0,1)        -> weight (1-u)v
    const float4 p2 = __ldg(P + 8);   // corner (1,0)        -> weight u(1-v)
    const float4 p3 = __ldg(P + 12);  // corner (1,1)        -> weight uv

    // X row = GROUPS float2's; group g uses X[b, 2g], X[b, 2g+1]
    const float2* Xp = reinterpret_cast<const float2*>(X) + g;
    // out row = GROUPS*OUT_DIM/4 = 2048 float4's
    float4* O = reinterpret_cast<float4*>(out) + (size_t)g * 4 + q;

#pragma unroll 4
    for (int i = 0; i < B_ITER; ++i) {
        const int b = b0 + i;
        if (b >= batch) break;

        const float2 xv = __ldg(Xp + (size_t)b * GROUPS);
        const float u = (fminf(fmaxf(xv.x, -1.0f), 1.0f) + 1.0f) * 0.5f;
        const float v = (fminf(fmaxf(xv.y, -1.0f), 1.0f) + 1.0f) * 0.5f;

        const float wD = u * v;              // (1,1)
        const float wC = u - wD;             // u(1-v)   -> (1,0)
        const float wB = v - wD;             // (1-u)v   -> (0,1)
        const float wA = 1.0f - u - v + wD;  // (1-u)(1-v)

        float4 o;
        o.x = fmaf(wA, p0.x, fmaf(wB, p1.x, fmaf(wC, p2.x, wD * p3.x)));
        o.y = fmaf(wA, p0.y, fmaf(wB, p1.y, fmaf(wC, p2.y, wD * p3.y)));
        o.z = fmaf(wA, p0.z, fmaf(wB, p1.z, fmaf(wC, p2.z, wD * p3.z)));
        o.w = fmaf(wA, p0.w, fmaf(wB, p1.w, fmaf(wC, p2.w, wD * p3.w)));

        // streaming store: 256 MiB output >> L2, don't pollute
        __stcs(O + (size_t)b * (GROUPS * OUT_DIM / 4), o);
    }
}

extern "C" void kernel_launch(void* const* d_in, const int* in_sizes, int n_in,
                              void* d_out, int out_size)
{
    // Identify X vs params by element count (X = B*1024, params = 512*4*16 = 32768)
    const float* X;
    const float* params;
    int szX;
    if (in_sizes[0] > in_sizes[1]) {
        X = (const float*)d_in[0]; params = (const float*)d_in[1]; szX = in_sizes[0];
    } else {
        X = (const float*)d_in[1]; params = (const float*)d_in[0]; szX = in_sizes[1];
    }
    const int batch = szX / (GROUPS * ARITY);

    dim3 block(256);
    dim3 grid(GROUPS / GPB, (batch + B_ITER - 1) / B_ITER);
    corner_bilinear_kernel<<<grid, block>>>(X, params, (float*)d_out, batch);
}

// round 8
// speedup vs baseline: 1.0012x; 1.0012x over previous
#include <cuda_runtime.h>
#include <cuda_bf16.h>

#define GROUPS   512
#define ARITY    2
#define OUT_DIM  16
#define GPB      64    // groups per block (64 groups * 4 dim-quads = 256 threads)
#define GRID_Y   128   // batch chunks -> B_ITER = batch/128 = 64 rows per block
#define CHUNK    8     // X-load prefetch depth (MLP per thread)

// out[b, g*16 + d] = bilinear interp of params[g, 0..3, d] at
// (u, v) = ((clip(x0,-1,1)+1)/2, (clip(x1,-1,1)+1)/2).
// Exact algebraic collapse of the midpoint-expanded 3x3 hat-basis contraction:
// inserted midpoints are exact averages, so the 3-pt hat interpolation on each
// axis is the straight line lerp(lo, hi, t/2).
__global__ __launch_bounds__(256) void corner_bilinear_kernel(
    const float* __restrict__ X,
    const float* __restrict__ params,
    float* __restrict__ out,
    int batch, int rows_per_block)
{
    const int tid = threadIdx.x;
    const int q   = tid & 3;          // dim-quad 0..3 (4 floats each)
    const int gl  = tid >> 2;         // local group 0..63
    const int g   = blockIdx.x * GPB + gl;
    const int b0  = blockIdx.y * rows_per_block;

    // params[g, c, d]: float4 index = g*16 + c*4 + q  (corner c = 2*c0 + c1)
    const float4* P = reinterpret_cast<const float4*>(params) + (size_t)g * 16 + q;
    const float4 p0 = __ldg(P + 0);   // (0,0) -> (1-u)(1-v)
    const float4 p1 = __ldg(P + 4);   // (0,1) -> (1-u)v
    const float4 p2 = __ldg(P + 8);   // (1,0) -> u(1-v)
    const float4 p3 = __ldg(P + 12);  // (1,1) -> uv

    // X row = GROUPS float2's; group g uses X[b, 2g], X[b, 2g+1]
    const float2* Xp = reinterpret_cast<const float2*>(X) + (size_t)b0 * GROUPS + g;
    // out row = GROUPS*OUT_DIM/4 = 2048 float4's
    float4* O = reinterpret_cast<float4*>(out)
              + (size_t)b0 * (GROUPS * OUT_DIM / 4) + (size_t)g * 4 + q;

    const int rows = min(rows_per_block, batch - b0);

    int i0 = 0;
    // fast path: full chunks (batch=8192, GRID_Y=128 -> rows=64, always exact)
    for (; i0 + CHUNK <= rows; i0 += CHUNK) {
        float2 xs[CHUNK];
        // front-batched loads: MLP_p1 = CHUNK, hides DRAM latency
        #pragma unroll
        for (int j = 0; j < CHUNK; ++j)
            xs[j] = __ldg(Xp + (size_t)(i0 + j) * GROUPS);

        #pragma unroll
        for (int j = 0; j < CHUNK; ++j) {
            const float u = (fminf(fmaxf(xs[j].x, -1.0f), 1.0f) + 1.0f) * 0.5f;
            const float v = (fminf(fmaxf(xs[j].y, -1.0f), 1.0f) + 1.0f) * 0.5f;

            const float wD = u * v;              // uv
            const float wC = u - wD;             // u(1-v)
            const float wB = v - wD;             // (1-u)v
            const float wA = 1.0f - u - v + wD;  // (1-u)(1-v)

            float4 o;
            o.x = fmaf(wA, p0.x, fmaf(wB, p1.x, fmaf(wC, p2.x, wD * p3.x)));
            o.y = fmaf(wA, p0.y, fmaf(wB, p1.y, fmaf(wC, p2.y, wD * p3.y)));
            o.z = fmaf(wA, p0.z, fmaf(wB, p1.z, fmaf(wC, p2.z, wD * p3.z)));
            o.w = fmaf(wA, p0.w, fmaf(wB, p1.w, fmaf(wC, p2.w, wD * p3.w)));

            // streaming store: 256 MiB output >> L2, evict early
            __stcs(O + (size_t)(i0 + j) * (GROUPS * OUT_DIM / 4), o);
        }
    }
    // tail (only if batch % (GRID_Y*CHUNK) != 0)
    for (; i0 < rows; ++i0) {
        const float2 xv = __ldg(Xp + (size_t)i0 * GROUPS);
        const float u = (fminf(fmaxf(xv.x, -1.0f), 1.0f) + 1.0f) * 0.5f;
        const float v = (fminf(fmaxf(xv.y, -1.0f), 1.0f) + 1.0f) * 0.5f;
        const float wD = u * v;
        const float wC = u - wD;
        const float wB = v - wD;
        const float wA = 1.0f - u - v + wD;
        float4 o;
        o.x = fmaf(wA, p0.x, fmaf(wB, p1.x, fmaf(wC, p2.x, wD * p3.x)));
        o.y = fmaf(wA, p0.y, fmaf(wB, p1.y, fmaf(wC, p2.y, wD * p3.y)));
        o.z = fmaf(wA, p0.z, fmaf(wB, p1.z, fmaf(wC, p2.z, wD * p3.z)));
        o.w = fmaf(wA, p0.w, fmaf(wB, p1.w, fmaf(wC, p2.w, wD * p3.w)));
        __stcs(O + (size_t)i0 * (GROUPS * OUT_DIM / 4), o);
    }
}

extern "C" void kernel_launch(void* const* d_in, const int* in_sizes, int n_in,
                              void* d_out, int out_size)
{
    // Identify X vs params by element count (X = B*1024, params = 512*4*16 = 32768)
    const float* X;
    const float* params;
    int szX;
    if (in_sizes[0] > in_sizes[1]) {
        X = (const float*)d_in[0]; params = (const float*)d_in[1]; szX = in_sizes[0];
    } else {
        X = (const float*)d_in[1]; params = (const float*)d_in[0]; szX = in_sizes[1];
    }
    const int batch = szX / (GROUPS * ARITY);
    const int rows_per_block = (batch + GRID_Y - 1) / GRID_Y;

    dim3 block(256);
    dim3 grid(GROUPS / GPB, GRID_Y);
    corner_bilinear_kernel<<<grid, block>>>(X, params, (float*)d_out,
                                            batch, rows_per_block);
}